// round 6
// baseline (speedup 1.0000x reference)
#include <cuda_runtime.h>
#include <cstddef>

// Problem dims
#define NROWS 32768          // B*S = 8*4096
#define EDIM  1024
#define MSIZE 2048

// ---------------- scratch (static device globals; no allocation) -------------
__device__ float       g_part[8192];
__device__ float       g_scal[8];          // 0: xmax, 1: hmax, 2: wscale_k, 3: wscale_o
__device__ signed char g_qx [(size_t)NROWS * EDIM];      // reused for qh
__device__ signed char g_qwk[(size_t)EDIM * EDIM];
__device__ signed char g_qwo[(size_t)EDIM * EDIM];
__device__ float       g_qk [(size_t)NROWS * EDIM];      // query_keys
__device__ float       g_sim[(size_t)NROWS * MSIZE];     // similarities / attn (in-place)
__device__ float       g_h  [(size_t)NROWS * EDIM];      // x + retrieved

// ---------------- reductions -------------------------------------------------
__global__ void absmax_part(const float* __restrict__ x, size_t n4, float* __restrict__ part) {
    const float4* x4 = (const float4*)x;
    float m = 0.f;
    for (size_t i = (size_t)blockIdx.x * blockDim.x + threadIdx.x; i < n4;
         i += (size_t)gridDim.x * blockDim.x) {
        float4 v = x4[i];
        m = fmaxf(m, fmaxf(fmaxf(fabsf(v.x), fabsf(v.y)), fmaxf(fabsf(v.z), fabsf(v.w))));
    }
    __shared__ float red[256];
    red[threadIdx.x] = m; __syncthreads();
    for (int s = 128; s > 0; s >>= 1) {
        if (threadIdx.x < s) red[threadIdx.x] = fmaxf(red[threadIdx.x], red[threadIdx.x + s]);
        __syncthreads();
    }
    if (threadIdx.x == 0) part[blockIdx.x] = red[0];
}

__global__ void abssum_part(const float* __restrict__ x, size_t n4, float* __restrict__ part) {
    const float4* x4 = (const float4*)x;
    float s = 0.f;
    for (size_t i = (size_t)blockIdx.x * blockDim.x + threadIdx.x; i < n4;
         i += (size_t)gridDim.x * blockDim.x) {
        float4 v = x4[i];
        s += fabsf(v.x) + fabsf(v.y) + fabsf(v.z) + fabsf(v.w);
    }
    __shared__ float red[256];
    red[threadIdx.x] = s; __syncthreads();
    for (int st = 128; st > 0; st >>= 1) {
        if (threadIdx.x < st) red[threadIdx.x] += red[threadIdx.x + st];
        __syncthreads();
    }
    if (threadIdx.x == 0) part[blockIdx.x] = red[0];
}

__global__ void finalize_max(const float* __restrict__ part, int npart, float* __restrict__ out) {
    float m = 0.f;
    for (int i = threadIdx.x; i < npart; i += 256) m = fmaxf(m, part[i]);
    __shared__ float red[256];
    red[threadIdx.x] = m; __syncthreads();
    for (int s = 128; s > 0; s >>= 1) {
        if (threadIdx.x < s) red[threadIdx.x] = fmaxf(red[threadIdx.x], red[threadIdx.x + s]);
        __syncthreads();
    }
    if (threadIdx.x == 0) out[0] = red[0];
}

__global__ void finalize_mean(const float* __restrict__ part, int npart, float* __restrict__ out, float n) {
    float s = 0.f;
    for (int i = threadIdx.x; i < npart; i += 256) s += part[i];
    __shared__ float red[256];
    red[threadIdx.x] = s; __syncthreads();
    for (int st = 128; st > 0; st >>= 1) {
        if (threadIdx.x < st) red[threadIdx.x] += red[threadIdx.x + st];
        __syncthreads();
    }
    if (threadIdx.x == 0) out[0] = __fdiv_rn(red[0], n);
}

// ---------------- quantization ----------------------------------------------
__global__ void quantize_act(const float* __restrict__ x, signed char* __restrict__ q,
                             const float* __restrict__ amax, size_t n4) {
    size_t i = (size_t)blockIdx.x * blockDim.x + threadIdx.x;
    if (i >= n4) return;
    float iscale = __fdiv_rn(amax[0], 127.0f);
    float4 v = ((const float4*)x)[i];
    char4 o;
    float r;
    r = rintf(__fdiv_rn(v.x, iscale)); r = fminf(fmaxf(r, -128.f), 127.f); o.x = (signed char)r;
    r = rintf(__fdiv_rn(v.y, iscale)); r = fminf(fmaxf(r, -128.f), 127.f); o.y = (signed char)r;
    r = rintf(__fdiv_rn(v.z, iscale)); r = fminf(fmaxf(r, -128.f), 127.f); o.z = (signed char)r;
    r = rintf(__fdiv_rn(v.w, iscale)); r = fminf(fmaxf(r, -128.f), 127.f); o.w = (signed char)r;
    ((char4*)q)[i] = o;
}

__global__ void quantize_w(const float* __restrict__ W, signed char* __restrict__ q,
                           const float* __restrict__ wscale, size_t n4) {
    size_t i = (size_t)blockIdx.x * blockDim.x + threadIdx.x;
    if (i >= n4) return;
    float thr = 0.5f * wscale[0];
    float4 v = ((const float4*)W)[i];
    char4 o;
    o.x = (fabsf(v.x) > thr) ? (v.x > 0.f ? 1 : -1) : 0;
    o.y = (fabsf(v.y) > thr) ? (v.y > 0.f ? 1 : -1) : 0;
    o.z = (fabsf(v.z) > thr) ? (v.z > 0.f ? 1 : -1) : 0;
    o.w = (fabsf(v.w) > thr) ? (v.w > 0.f ? 1 : -1) : 0;
    ((char4*)q)[i] = o;
}

// ---------------- int8 GEMM (dp4a): C[N,M] = A[N,K] * B[M,K]^T * s + bias ----
__global__ __launch_bounds__(256)
void igemm_nt(const signed char* __restrict__ A8, const signed char* __restrict__ B8,
              const float* __restrict__ bias,
              const float* __restrict__ wscale, const float* __restrict__ amax,
              float* __restrict__ C, int N, int M, int K) {
    const int Ki = K >> 2;                 // packed ints per row
    __shared__ int As[8][132];
    __shared__ int Bs[8][132];
    const int bm = blockIdx.y * 128;
    const int bn = blockIdx.x * 128;
    const int tid = threadIdx.x;
    const int tx = tid & 15, ty = tid >> 4;
    const int lr = tid >> 1;
    const int lk = (tid & 1) * 4;
    const int* Ap = (const int*)A8 + (size_t)(bm + lr) * Ki + lk;
    const int* Bp = (const int*)B8 + (size_t)(bn + lr) * Ki + lk;
    int acc[8][8] = {};
    for (int k0 = 0; k0 < Ki; k0 += 8) {
        int4 a4 = *(const int4*)(Ap + k0);
        int4 b4 = *(const int4*)(Bp + k0);
        As[lk + 0][lr] = a4.x; As[lk + 1][lr] = a4.y; As[lk + 2][lr] = a4.z; As[lk + 3][lr] = a4.w;
        Bs[lk + 0][lr] = b4.x; Bs[lk + 1][lr] = b4.y; Bs[lk + 2][lr] = b4.z; Bs[lk + 3][lr] = b4.w;
        __syncthreads();
#pragma unroll
        for (int k = 0; k < 8; k++) {
            int4 a0 = *(const int4*)&As[k][ty * 8];
            int4 a1 = *(const int4*)&As[k][ty * 8 + 4];
            int4 b0 = *(const int4*)&Bs[k][tx * 8];
            int4 b1 = *(const int4*)&Bs[k][tx * 8 + 4];
            int a[8] = {a0.x, a0.y, a0.z, a0.w, a1.x, a1.y, a1.z, a1.w};
            int b[8] = {b0.x, b0.y, b0.z, b0.w, b1.x, b1.y, b1.z, b1.w};
#pragma unroll
            for (int i = 0; i < 8; i++)
#pragma unroll
                for (int j = 0; j < 8; j++)
                    acc[i][j] = __dp4a(a[i], b[j], acc[i][j]);
        }
        __syncthreads();
    }
    const float scale = wscale[0] * __fdiv_rn(amax[0], 127.0f);
#pragma unroll
    for (int i = 0; i < 8; i++) {
        size_t row = (size_t)(bm + ty * 8 + i);
        float* Crow = C + row * M + bn + tx * 8;
        const float* brow = bias + bn + tx * 8;
#pragma unroll
        for (int j = 0; j < 8; j++) Crow[j] = (float)acc[i][j] * scale + brow[j];
    }
}

// ---------------- fp32 GEMM NT: C[N,M] = alpha * A[N,K] * B[M,K]^T -----------
__global__ __launch_bounds__(256)
void sgemm_nt(const float* __restrict__ A, const float* __restrict__ B,
              float* __restrict__ C, int N, int M, int K, float alpha) {
    __shared__ float As[8][132];
    __shared__ float Bs[8][132];
    const int bm = blockIdx.y * 128;
    const int bn = blockIdx.x * 128;
    const int tid = threadIdx.x;
    const int tx = tid & 15, ty = tid >> 4;
    const int lr = tid >> 1;
    const int lk = (tid & 1) * 4;
    const float* Ap = A + (size_t)(bm + lr) * K + lk;
    const float* Bp = B + (size_t)(bn + lr) * K + lk;
    float acc[8][8] = {};
    for (int k0 = 0; k0 < K; k0 += 8) {
        float4 a4 = *(const float4*)(Ap + k0);
        float4 b4 = *(const float4*)(Bp + k0);
        As[lk + 0][lr] = a4.x; As[lk + 1][lr] = a4.y; As[lk + 2][lr] = a4.z; As[lk + 3][lr] = a4.w;
        Bs[lk + 0][lr] = b4.x; Bs[lk + 1][lr] = b4.y; Bs[lk + 2][lr] = b4.z; Bs[lk + 3][lr] = b4.w;
        __syncthreads();
#pragma unroll
        for (int k = 0; k < 8; k++) {
            float4 a0 = *(const float4*)&As[k][ty * 8];
            float4 a1 = *(const float4*)&As[k][ty * 8 + 4];
            float4 b0 = *(const float4*)&Bs[k][tx * 8];
            float4 b1 = *(const float4*)&Bs[k][tx * 8 + 4];
            float a[8] = {a0.x, a0.y, a0.z, a0.w, a1.x, a1.y, a1.z, a1.w};
            float b[8] = {b0.x, b0.y, b0.z, b0.w, b1.x, b1.y, b1.z, b1.w};
#pragma unroll
            for (int i = 0; i < 8; i++)
#pragma unroll
                for (int j = 0; j < 8; j++)
                    acc[i][j] += a[i] * b[j];
        }
        __syncthreads();
    }
#pragma unroll
    for (int i = 0; i < 8; i++) {
        size_t row = (size_t)(bm + ty * 8 + i);
        float* Crow = C + row * M + bn + tx * 8;
#pragma unroll
        for (int j = 0; j < 8; j++) Crow[j] = acc[i][j] * alpha;
    }
}

// ------------- fp32 GEMM NN + residual: C = A[N,K]*B[K,M] + X ----------------
__global__ __launch_bounds__(256)
void sgemm_nn_add(const float* __restrict__ A, const float* __restrict__ B,
                  const float* __restrict__ X, float* __restrict__ C,
                  int N, int M, int K) {
    __shared__ float As[8][132];
    __shared__ float Bs[8][132];
    const int bm = blockIdx.y * 128;
    const int bn = blockIdx.x * 128;
    const int tid = threadIdx.x;
    const int tx = tid & 15, ty = tid >> 4;
    const int lr = tid >> 1;
    const int lk = (tid & 1) * 4;
    const int lkb = tid >> 5;              // 0..7 (k row of B tile)
    const int lcb = (tid & 31) * 4;        // col in B tile
    const float* Ap = A + (size_t)(bm + lr) * K + lk;
    const float* Bp = B + (size_t)lkb * M + bn + lcb;
    float acc[8][8] = {};
    for (int k0 = 0; k0 < K; k0 += 8) {
        float4 a4 = *(const float4*)(Ap + k0);
        float4 b4 = *(const float4*)(Bp + (size_t)k0 * M);
        As[lk + 0][lr] = a4.x; As[lk + 1][lr] = a4.y; As[lk + 2][lr] = a4.z; As[lk + 3][lr] = a4.w;
        *(float4*)&Bs[lkb][lcb] = b4;
        __syncthreads();
#pragma unroll
        for (int k = 0; k < 8; k++) {
            float4 a0 = *(const float4*)&As[k][ty * 8];
            float4 a1 = *(const float4*)&As[k][ty * 8 + 4];
            float4 b0 = *(const float4*)&Bs[k][tx * 8];
            float4 b1 = *(const float4*)&Bs[k][tx * 8 + 4];
            float a[8] = {a0.x, a0.y, a0.z, a0.w, a1.x, a1.y, a1.z, a1.w};
            float b[8] = {b0.x, b0.y, b0.z, b0.w, b1.x, b1.y, b1.z, b1.w};
#pragma unroll
            for (int i = 0; i < 8; i++)
#pragma unroll
                for (int j = 0; j < 8; j++)
                    acc[i][j] += a[i] * b[j];
        }
        __syncthreads();
    }
#pragma unroll
    for (int i = 0; i < 8; i++) {
        size_t row = (size_t)(bm + ty * 8 + i);
        float* Crow = C + row * M + bn + tx * 8;
        const float* Xrow = X + row * M + bn + tx * 8;
#pragma unroll
        for (int j = 0; j < 8; j++) Crow[j] = acc[i][j] + Xrow[j];
    }
}

// ---------------- row softmax over MSIZE cols --------------------------------
__global__ void softmax_rows(float* __restrict__ S) {
    const size_t row = blockIdx.x;
    float* p = S + row * (size_t)MSIZE;
    const int tid = threadIdx.x;
    float v[8];
#pragma unroll
    for (int i = 0; i < 8; i++) v[i] = p[tid + i * 256];
    float m = v[0];
#pragma unroll
    for (int i = 1; i < 8; i++) m = fmaxf(m, v[i]);
    __shared__ float red[256];
    red[tid] = m; __syncthreads();
    for (int s = 128; s > 0; s >>= 1) {
        if (tid < s) red[tid] = fmaxf(red[tid], red[tid + s]);
        __syncthreads();
    }
    const float rowmax = red[0];
    __syncthreads();
    float sum = 0.f;
#pragma unroll
    for (int i = 0; i < 8; i++) { v[i] = expf(v[i] - rowmax); sum += v[i]; }
    red[tid] = sum; __syncthreads();
    for (int s = 128; s > 0; s >>= 1) {
        if (tid < s) red[tid] += red[tid + s];
        __syncthreads();
    }
    const float inv = __fdiv_rn(1.0f, red[0]);
#pragma unroll
    for (int i = 0; i < 8; i++) p[tid + i * 256] = v[i] * inv;
}

// ---------------- launch -----------------------------------------------------
extern "C" void kernel_launch(void* const* d_in, const int* in_sizes, int n_in,
                              void* d_out, int out_size) {
    const float* x  = (const float*)d_in[0];
    const float* mk = (const float*)d_in[1];
    const float* mv = (const float*)d_in[2];
    const float* Wk = (const float*)d_in[3];
    const float* bk = (const float*)d_in[4];
    // d_in[5], d_in[6] (Wv, bv) are dead: _query_values never reaches the output.
    const float* Wo = (const float*)d_in[7];
    const float* bo = (const float*)d_in[8];
    float* out = (float*)d_out;

    void *pp, *ps, *pqx, *pqwk, *pqwo, *pqk, *psim, *ph;
    cudaGetSymbolAddress(&pp,  g_part);
    cudaGetSymbolAddress(&ps,  g_scal);
    cudaGetSymbolAddress(&pqx, g_qx);
    cudaGetSymbolAddress(&pqwk, g_qwk);
    cudaGetSymbolAddress(&pqwo, g_qwo);
    cudaGetSymbolAddress(&pqk, g_qk);
    cudaGetSymbolAddress(&psim, g_sim);
    cudaGetSymbolAddress(&ph,  g_h);
    float* part = (float*)pp;
    float* scal = (float*)ps;
    signed char* qx  = (signed char*)pqx;
    signed char* qwk = (signed char*)pqwk;
    signed char* qwo = (signed char*)pqwo;
    float* qk  = (float*)pqk;
    float* sim = (float*)psim;
    float* h   = (float*)ph;

    const size_t nx = (size_t)NROWS * EDIM;      // 33.5M
    const size_t nw = (size_t)EDIM * EDIM;       // 1M

    // scales
    absmax_part<<<2048, 256>>>(x, nx / 4, part);
    finalize_max<<<1, 256>>>(part, 2048, scal + 0);
    abssum_part<<<1024, 256>>>(Wk, nw / 4, part + 2048);
    finalize_mean<<<1, 256>>>(part + 2048, 1024, scal + 2, (float)nw);
    abssum_part<<<1024, 256>>>(Wo, nw / 4, part + 6144);
    finalize_mean<<<1, 256>>>(part + 6144, 1024, scal + 3, (float)nw);

    // quantize
    quantize_act<<<(unsigned)(nx / 4 / 256), 256>>>(x, qx, scal + 0, nx / 4);
    quantize_w<<<(unsigned)(nw / 4 / 256), 256>>>(Wk, qwk, scal + 2, nw / 4);
    quantize_w<<<(unsigned)(nw / 4 / 256), 256>>>(Wo, qwo, scal + 3, nw / 4);

    // query_keys = bitnet(x, Wk, bk)
    igemm_nt<<<dim3(EDIM / 128, NROWS / 128), 256>>>(qx, qwk, bk, scal + 2, scal + 0,
                                                     qk, NROWS, EDIM, EDIM);
    // similarities (scaled by 1/sqrt(1024) = 1/32)
    sgemm_nt<<<dim3(MSIZE / 128, NROWS / 128), 256>>>(qk, mk, sim, NROWS, MSIZE, EDIM, 0.03125f);
    // softmax over memory slots
    softmax_rows<<<NROWS, 256>>>(sim);
    // h = x + attn @ memory_values
    sgemm_nn_add<<<dim3(EDIM / 128, NROWS / 128), 256>>>(sim, mv, x, h, NROWS, EDIM, MSIZE);

    // output = bitnet(h, Wo, bo)
    absmax_part<<<2048, 256>>>(h, nx / 4, part + 4096);
    finalize_max<<<1, 256>>>(part + 4096, 2048, scal + 1);
    quantize_act<<<(unsigned)(nx / 4 / 256), 256>>>(h, qx, scal + 1, nx / 4);
    igemm_nt<<<dim3(EDIM / 128, NROWS / 128), 256>>>(qx, qwo, bo, scal + 3, scal + 1,
                                                     out, NROWS, EDIM, EDIM);
}

// round 7
// speedup vs baseline: 1.3049x; 1.3049x over previous
#include <cuda_runtime.h>
#include <cstddef>

#define NROWS 32768
#define EDIM  1024
#define MSIZE 2048

// scratch
__device__ float       g_part[4096];
__device__ float       g_scal[8]; // 0 xmax,1 hmax,2 wsk,3 wso,4 alpha1,5 alpha2,6 gmax
__device__ signed char g_qx [(size_t)NROWS * EDIM];   // qx, reused for qh
__device__ signed char g_qwk[(size_t)EDIM * EDIM];
__device__ signed char g_qwo[(size_t)EDIM * EDIM];
__device__ float       g_G  [(size_t)MSIZE * EDIM];
__device__ signed char g_g1 [(size_t)MSIZE * EDIM];
__device__ signed char g_g2 [(size_t)MSIZE * EDIM];
__device__ float       g_c  [MSIZE];
__device__ float       g_sim[(size_t)NROWS * MSIZE];
__device__ float       g_h  [(size_t)NROWS * EDIM];

// ---------------- reductions ------------------------------------------------
__global__ void absmax_part(const float* __restrict__ x, size_t n4, float* __restrict__ part) {
    const float4* x4 = (const float4*)x;
    float m = 0.f;
    for (size_t i = (size_t)blockIdx.x * blockDim.x + threadIdx.x; i < n4;
         i += (size_t)gridDim.x * blockDim.x) {
        float4 v = x4[i];
        m = fmaxf(m, fmaxf(fmaxf(fabsf(v.x), fabsf(v.y)), fmaxf(fabsf(v.z), fabsf(v.w))));
    }
    __shared__ float red[256];
    red[threadIdx.x] = m; __syncthreads();
    for (int s = 128; s > 0; s >>= 1) {
        if (threadIdx.x < s) red[threadIdx.x] = fmaxf(red[threadIdx.x], red[threadIdx.x + s]);
        __syncthreads();
    }
    if (threadIdx.x == 0) part[blockIdx.x] = red[0];
}

__global__ void abssum_part(const float* __restrict__ x, size_t n4, float* __restrict__ part) {
    const float4* x4 = (const float4*)x;
    float s = 0.f;
    for (size_t i = (size_t)blockIdx.x * blockDim.x + threadIdx.x; i < n4;
         i += (size_t)gridDim.x * blockDim.x) {
        float4 v = x4[i];
        s += fabsf(v.x) + fabsf(v.y) + fabsf(v.z) + fabsf(v.w);
    }
    __shared__ float red[256];
    red[threadIdx.x] = s; __syncthreads();
    for (int st = 128; st > 0; st >>= 1) {
        if (threadIdx.x < st) red[threadIdx.x] += red[threadIdx.x + st];
        __syncthreads();
    }
    if (threadIdx.x == 0) part[blockIdx.x] = red[0];
}

__global__ void finalize_max(const float* __restrict__ part, int npart, float* __restrict__ out) {
    __shared__ float red[256];
    float m = 0.f;
    for (int i = threadIdx.x; i < npart; i += 256) m = fmaxf(m, part[i]);
    red[threadIdx.x] = m; __syncthreads();
    for (int s = 128; s > 0; s >>= 1) {
        if (threadIdx.x < s) red[threadIdx.x] = fmaxf(red[threadIdx.x], red[threadIdx.x + s]);
        __syncthreads();
    }
    if (threadIdx.x == 0) out[0] = red[0];
}

__global__ void finalize_mean(const float* __restrict__ part, int npart, float* __restrict__ out, float n) {
    __shared__ float red[256];
    float s = 0.f;
    for (int i = threadIdx.x; i < npart; i += 256) s += part[i];
    red[threadIdx.x] = s; __syncthreads();
    for (int st = 128; st > 0; st >>= 1) {
        if (threadIdx.x < st) red[threadIdx.x] += red[threadIdx.x + st];
        __syncthreads();
    }
    if (threadIdx.x == 0) out[0] = __fdiv_rn(red[0], n);
}

// ---------------- quantization ----------------------------------------------
__global__ void quantize_act(const float* __restrict__ x, signed char* __restrict__ q,
                             const float* __restrict__ amax, size_t n4) {
    size_t i = (size_t)blockIdx.x * blockDim.x + threadIdx.x;
    if (i >= n4) return;
    float iscale = __fdiv_rn(amax[0], 127.0f);
    float4 v = ((const float4*)x)[i];
    char4 o; float r;
    r = rintf(__fdiv_rn(v.x, iscale)); r = fminf(fmaxf(r, -128.f), 127.f); o.x = (signed char)r;
    r = rintf(__fdiv_rn(v.y, iscale)); r = fminf(fmaxf(r, -128.f), 127.f); o.y = (signed char)r;
    r = rintf(__fdiv_rn(v.z, iscale)); r = fminf(fmaxf(r, -128.f), 127.f); o.z = (signed char)r;
    r = rintf(__fdiv_rn(v.w, iscale)); r = fminf(fmaxf(r, -128.f), 127.f); o.w = (signed char)r;
    ((char4*)q)[i] = o;
}

__global__ void quantize_w(const float* __restrict__ W, signed char* __restrict__ q,
                           const float* __restrict__ wscale, size_t n4) {
    size_t i = (size_t)blockIdx.x * blockDim.x + threadIdx.x;
    if (i >= n4) return;
    float thr = 0.5f * wscale[0];
    float4 v = ((const float4*)W)[i];
    char4 o;
    o.x = (fabsf(v.x) > thr) ? (v.x > 0.f ? 1 : -1) : 0;
    o.y = (fabsf(v.y) > thr) ? (v.y > 0.f ? 1 : -1) : 0;
    o.z = (fabsf(v.z) > thr) ? (v.z > 0.f ? 1 : -1) : 0;
    o.w = (fabsf(v.w) > thr) ? (v.w > 0.f ? 1 : -1) : 0;
    ((char4*)q)[i] = o;
}

// G 2-level int8 split: G = GS1*g1 + GS2*g2 + r2, GS1=gmax/127, GS2=GS1/254
__global__ void quantize_g(const float* __restrict__ G, signed char* __restrict__ q1,
                           signed char* __restrict__ q2, const float* __restrict__ gmax) {
    size_t i = (size_t)blockIdx.x * blockDim.x + threadIdx.x;
    if (i >= (size_t)MSIZE * EDIM) return;
    float GS1 = __fdiv_rn(gmax[0], 127.0f);
    float GS2 = __fdiv_rn(GS1, 254.0f);
    float g = G[i];
    float a = rintf(__fdiv_rn(g, GS1)); a = fminf(fmaxf(a, -127.f), 127.f);
    float r = g - GS1 * a;
    float b = rintf(__fdiv_rn(r, GS2)); b = fminf(fmaxf(b, -127.f), 127.f);
    q1[i] = (signed char)a; q2[i] = (signed char)b;
}

// scal[4] = 0.03125 * wsk * xmax/127 * gmax/127 ; scal[5] = scal[4]/254
__global__ void combine_scales(float* __restrict__ scal) {
    if (threadIdx.x == 0) {
        float a = 0.03125f * scal[2] * __fdiv_rn(scal[0], 127.0f) * __fdiv_rn(scal[6], 127.0f);
        scal[4] = a; scal[5] = __fdiv_rn(a, 254.0f);
    }
}

// ------- G = mk[M2,K] @ qWk[K,E]  (fp32 NN, int8 B) --------------------------
__global__ __launch_bounds__(256)
void gt_gemm(const float* __restrict__ A, const signed char* __restrict__ B8,
             float* __restrict__ C, int N, int M, int K) {
    __shared__ float As[8][132];
    __shared__ float Bs[8][132];
    const int bm = blockIdx.y * 128, bn = blockIdx.x * 128;
    const int tid = threadIdx.x;
    const int tx = tid & 15, ty = tid >> 4;
    const int lr = tid >> 1, lk = (tid & 1) * 4;
    const int lkb = tid >> 5, lcb = (tid & 31) * 4;
    const float* Ap = A + (size_t)(bm + lr) * K + lk;
    const signed char* Bp = B8 + (size_t)lkb * M + bn + lcb;
    float acc[8][8] = {};
    for (int k0 = 0; k0 < K; k0 += 8) {
        float4 a4 = *(const float4*)(Ap + k0);
        char4 bc = *(const char4*)(Bp + (size_t)k0 * M);
        As[lk + 0][lr] = a4.x; As[lk + 1][lr] = a4.y; As[lk + 2][lr] = a4.z; As[lk + 3][lr] = a4.w;
        Bs[lkb][lcb + 0] = (float)bc.x; Bs[lkb][lcb + 1] = (float)bc.y;
        Bs[lkb][lcb + 2] = (float)bc.z; Bs[lkb][lcb + 3] = (float)bc.w;
        __syncthreads();
#pragma unroll
        for (int k = 0; k < 8; k++) {
            float4 a0 = *(const float4*)&As[k][ty * 8];
            float4 a1 = *(const float4*)&As[k][ty * 8 + 4];
            float4 b0 = *(const float4*)&Bs[k][tx * 8];
            float4 b1 = *(const float4*)&Bs[k][tx * 8 + 4];
            float a[8] = {a0.x, a0.y, a0.z, a0.w, a1.x, a1.y, a1.z, a1.w};
            float b[8] = {b0.x, b0.y, b0.z, b0.w, b1.x, b1.y, b1.z, b1.w};
#pragma unroll
            for (int i = 0; i < 8; i++)
#pragma unroll
                for (int j = 0; j < 8; j++) acc[i][j] += a[i] * b[j];
        }
        __syncthreads();
    }
#pragma unroll
    for (int i = 0; i < 8; i++) {
        float* Crow = C + (size_t)(bm + ty * 8 + i) * M + bn + tx * 8;
#pragma unroll
        for (int j = 0; j < 8; j++) Crow[j] = acc[i][j];
    }
}

// ---------------- int8 tensor-core GEMM NT -----------------------------------
__device__ __forceinline__ void mma_s8(int& c0, int& c1, int& c2, int& c3,
                                       int a0, int a1, int a2, int a3, int b0, int b1) {
    asm volatile("mma.sync.aligned.m16n8k32.row.col.s32.s8.s8.s32 "
                 "{%0,%1,%2,%3}, {%4,%5,%6,%7}, {%8,%9}, {%0,%1,%2,%3};"
                 : "+r"(c0), "+r"(c1), "+r"(c2), "+r"(c3)
                 : "r"(a0), "r"(a1), "r"(a2), "r"(a3), "r"(b0), "r"(b1));
}

// v = hscale*(p1?)*(p2?) * (A8[N,K] @ B8[M,K]^T)
// beta==0: C = v + bias[m] ; beta==1: C += v
__global__ __launch_bounds__(256)
void imma_nt(const signed char* __restrict__ A8, const signed char* __restrict__ B8,
             float* __restrict__ C, const float* __restrict__ bias,
             const float* __restrict__ p1, const float* __restrict__ p2,
             float hscale, int beta, int M, int K) {
    const int Ki = K >> 2;
    __shared__ int As[8][132];
    __shared__ int Bs[8][132];
    const int bm = blockIdx.y * 128, bn = blockIdx.x * 128;
    const int tid = threadIdx.x;
    const int lr = tid >> 1, lk = (tid & 1) * 4;
    const int warp = tid >> 5, lane = tid & 31;
    const int wm = (warp & 1) * 64, wn = (warp >> 1) * 32;
    const int quad = lane >> 2, qi = lane & 3;
    const int* Ap = (const int*)A8 + (size_t)(bm + lr) * Ki + lk;
    const int* Bp = (const int*)B8 + (size_t)(bn + lr) * Ki + lk;
    int acc[4][4][4] = {};
    for (int k0 = 0; k0 < Ki; k0 += 8) {
        int4 a4 = *(const int4*)(Ap + k0);
        int4 b4 = *(const int4*)(Bp + k0);
        As[lk + 0][lr] = a4.x; As[lk + 1][lr] = a4.y; As[lk + 2][lr] = a4.z; As[lk + 3][lr] = a4.w;
        Bs[lk + 0][lr] = b4.x; Bs[lk + 1][lr] = b4.y; Bs[lk + 2][lr] = b4.z; Bs[lk + 3][lr] = b4.w;
        __syncthreads();
        int af[4][4], bf[4][2];
#pragma unroll
        for (int mt = 0; mt < 4; mt++) {
            int rb = wm + mt * 16 + quad;
            af[mt][0] = As[qi][rb];     af[mt][1] = As[qi][rb + 8];
            af[mt][2] = As[qi + 4][rb]; af[mt][3] = As[qi + 4][rb + 8];
        }
#pragma unroll
        for (int nt = 0; nt < 4; nt++) {
            int cb = wn + nt * 8 + quad;
            bf[nt][0] = Bs[qi][cb]; bf[nt][1] = Bs[qi + 4][cb];
        }
#pragma unroll
        for (int mt = 0; mt < 4; mt++)
#pragma unroll
            for (int nt = 0; nt < 4; nt++)
                mma_s8(acc[mt][nt][0], acc[mt][nt][1], acc[mt][nt][2], acc[mt][nt][3],
                       af[mt][0], af[mt][1], af[mt][2], af[mt][3], bf[nt][0], bf[nt][1]);
        __syncthreads();
    }
    float alpha = hscale;
    if (p1) alpha *= p1[0];
    if (p2) alpha *= __fdiv_rn(p2[0], 127.0f);
#pragma unroll
    for (int mt = 0; mt < 4; mt++) {
#pragma unroll
        for (int nt = 0; nt < 4; nt++) {
            int row = bm + wm + mt * 16 + quad;
            int col = bn + wn + nt * 8 + qi * 2;
            float* C0 = C + (size_t)row * M + col;
            float* C1 = C + (size_t)(row + 8) * M + col;
            float v0 = (float)acc[mt][nt][0] * alpha;
            float v1 = (float)acc[mt][nt][1] * alpha;
            float v2 = (float)acc[mt][nt][2] * alpha;
            float v3 = (float)acc[mt][nt][3] * alpha;
            if (beta) { C0[0] += v0; C0[1] += v1; C1[0] += v2; C1[1] += v3; }
            else {
                float b0 = bias ? bias[col] : 0.f;
                float b1 = bias ? bias[col + 1] : 0.f;
                C0[0] = v0 + b0; C0[1] = v1 + b1; C1[0] = v2 + b0; C1[1] = v3 + b1;
            }
        }
    }
}

// ---------------- c[m] = dot(mk[m,:], bk) ------------------------------------
__global__ void cvec_k(const float* __restrict__ mk, const float* __restrict__ bk,
                       float* __restrict__ c) {
    int m = blockIdx.x * 8 + (threadIdx.x >> 5);
    int lane = threadIdx.x & 31;
    const float4* row = (const float4*)(mk + (size_t)m * EDIM);
    const float4* b4 = (const float4*)bk;
    float s = 0.f;
    for (int i = lane; i < EDIM / 4; i += 32) {
        float4 a = row[i], b = b4[i];
        s += a.x * b.x + a.y * b.y + a.z * b.z + a.w * b.w;
    }
    for (int o = 16; o > 0; o >>= 1) s += __shfl_xor_sync(0xffffffffu, s, o);
    if (lane == 0) c[m] = s;
}

// ---------------- row softmax (+ c[m]/32) ------------------------------------
__global__ void softmax_rows(float* __restrict__ S, const float* __restrict__ c) {
    const size_t row = blockIdx.x;
    float* p = S + row * (size_t)MSIZE;
    const int tid = threadIdx.x;
    float v[8];
#pragma unroll
    for (int i = 0; i < 8; i++) v[i] = p[tid + i * 256] + c[tid + i * 256] * 0.03125f;
    float m = v[0];
#pragma unroll
    for (int i = 1; i < 8; i++) m = fmaxf(m, v[i]);
    __shared__ float red[256];
    red[tid] = m; __syncthreads();
    for (int s = 128; s > 0; s >>= 1) {
        if (tid < s) red[tid] = fmaxf(red[tid], red[tid + s]);
        __syncthreads();
    }
    const float rowmax = red[0];
    __syncthreads();
    float sum = 0.f;
#pragma unroll
    for (int i = 0; i < 8; i++) { v[i] = expf(v[i] - rowmax); sum += v[i]; }
    red[tid] = sum; __syncthreads();
    for (int s = 128; s > 0; s >>= 1) {
        if (tid < s) red[tid] += red[tid + s];
        __syncthreads();
    }
    const float inv = __fdiv_rn(1.0f, red[0]);
#pragma unroll
    for (int i = 0; i < 8; i++) p[tid + i * 256] = v[i] * inv;
}

// ------------- fp32 GEMM NN + residual: C = A[N,K]*B[K,M] + X ----------------
__global__ __launch_bounds__(256)
void sgemm_nn_add(const float* __restrict__ A, const float* __restrict__ B,
                  const float* __restrict__ X, float* __restrict__ C,
                  int N, int M, int K) {
    __shared__ float As[8][132];
    __shared__ float Bs[8][132];
    const int bm = blockIdx.y * 128, bn = blockIdx.x * 128;
    const int tid = threadIdx.x;
    const int tx = tid & 15, ty = tid >> 4;
    const int lr = tid >> 1, lk = (tid & 1) * 4;
    const int lkb = tid >> 5, lcb = (tid & 31) * 4;
    const float* Ap = A + (size_t)(bm + lr) * K + lk;
    const float* Bp = B + (size_t)lkb * M + bn + lcb;
    float acc[8][8] = {};
    for (int k0 = 0; k0 < K; k0 += 8) {
        float4 a4 = *(const float4*)(Ap + k0);
        float4 b4 = *(const float4*)(Bp + (size_t)k0 * M);
        As[lk + 0][lr] = a4.x; As[lk + 1][lr] = a4.y; As[lk + 2][lr] = a4.z; As[lk + 3][lr] = a4.w;
        *(float4*)&Bs[lkb][lcb] = b4;
        __syncthreads();
#pragma unroll
        for (int k = 0; k < 8; k++) {
            float4 a0 = *(const float4*)&As[k][ty * 8];
            float4 a1 = *(const float4*)&As[k][ty * 8 + 4];
            float4 b0 = *(const float4*)&Bs[k][tx * 8];
            float4 b1 = *(const float4*)&Bs[k][tx * 8 + 4];
            float a[8] = {a0.x, a0.y, a0.z, a0.w, a1.x, a1.y, a1.z, a1.w};
            float b[8] = {b0.x, b0.y, b0.z, b0.w, b1.x, b1.y, b1.z, b1.w};
#pragma unroll
            for (int i = 0; i < 8; i++)
#pragma unroll
                for (int j = 0; j < 8; j++) acc[i][j] += a[i] * b[j];
        }
        __syncthreads();
    }
#pragma unroll
    for (int i = 0; i < 8; i++) {
        size_t row = (size_t)(bm + ty * 8 + i);
        float* Crow = C + row * M + bn + tx * 8;
        const float* Xrow = X + row * M + bn + tx * 8;
#pragma unroll
        for (int j = 0; j < 8; j++) Crow[j] = acc[i][j] + Xrow[j];
    }
}

// ---------------- launch -----------------------------------------------------
extern "C" void kernel_launch(void* const* d_in, const int* in_sizes, int n_in,
                              void* d_out, int out_size) {
    const float* x  = (const float*)d_in[0];
    const float* mk = (const float*)d_in[1];
    const float* mv = (const float*)d_in[2];
    const float* Wk = (const float*)d_in[3];
    const float* bk = (const float*)d_in[4];
    // d_in[5], d_in[6] (Wv, bv) dead: _query_values never reaches output.
    const float* Wo = (const float*)d_in[7];
    const float* bo = (const float*)d_in[8];
    float* out = (float*)d_out;

    void *p0,*p1,*p2,*p3,*p4,*p5,*p6,*p7,*p8,*p9;
    cudaGetSymbolAddress(&p0, g_part); cudaGetSymbolAddress(&p1, g_scal);
    cudaGetSymbolAddress(&p2, g_qx);   cudaGetSymbolAddress(&p3, g_qwk);
    cudaGetSymbolAddress(&p4, g_qwo);  cudaGetSymbolAddress(&p5, g_G);
    cudaGetSymbolAddress(&p6, g_g1);   cudaGetSymbolAddress(&p7, g_g2);
    cudaGetSymbolAddress(&p8, g_sim);  cudaGetSymbolAddress(&p9, g_h);
    float* part = (float*)p0;  float* scal = (float*)p1;
    signed char* qx = (signed char*)p2;
    signed char* qwk = (signed char*)p3;
    signed char* qwo = (signed char*)p4;
    float* G = (float*)p5;
    signed char* g1 = (signed char*)p6;
    signed char* g2 = (signed char*)p7;
    float* sim = (float*)p8;  float* h = (float*)p9;
    void* pc; cudaGetSymbolAddress(&pc, g_c); float* cvec = (float*)pc;

    const size_t nx = (size_t)NROWS * EDIM;
    const size_t nw = (size_t)EDIM * EDIM;
    const size_t ng = (size_t)MSIZE * EDIM;

    absmax_part<<<2048, 256>>>(x, nx / 4, part);                         // 0
    finalize_max<<<1, 256>>>(part, 2048, scal + 0);                      // 1
    abssum_part<<<512, 256>>>(Wk, nw / 4, part + 2048);                  // 2
    finalize_mean<<<1, 256>>>(part + 2048, 512, scal + 2, (float)nw);    // 3
    quantize_w<<<(unsigned)(nw / 4 / 256), 256>>>(Wk, qwk, scal + 2, nw / 4); // 4
    gt_gemm<<<dim3(EDIM / 128, MSIZE / 128), 256>>>(mk, qwk, G, MSIZE, EDIM, EDIM); // 5 (ncu)
    absmax_part<<<512, 256>>>(G, ng / 4, part);                          // 6
    finalize_max<<<1, 256>>>(part, 512, scal + 6);                       // 7
    combine_scales<<<1, 32>>>(scal);                                     // 8
    quantize_g<<<(unsigned)((ng + 255) / 256), 256>>>(G, g1, g2, scal + 6); // 9
    quantize_act<<<(unsigned)(nx / 4 / 256), 256>>>(x, qx, scal + 0, nx / 4); // 10
    abssum_part<<<512, 256>>>(Wo, nw / 4, part + 2048);                  // 11
    finalize_mean<<<1, 256>>>(part + 2048, 512, scal + 3, (float)nw);    // 12
    quantize_w<<<(unsigned)(nw / 4 / 256), 256>>>(Wo, qwo, scal + 3, nw / 4); // 13
    cvec_k<<<MSIZE / 8, 256>>>(mk, bk, cvec);                            // 14
    // sim = alpha1*(qx@g1^T) + alpha2*(qx@g2^T)
    imma_nt<<<dim3(MSIZE / 128, NROWS / 128), 256>>>(qx, g1, sim, nullptr,
        scal + 4, nullptr, 1.0f, 0, MSIZE, EDIM);                        // 15
    imma_nt<<<dim3(MSIZE / 128, NROWS / 128), 256>>>(qx, g2, sim, nullptr,
        scal + 5, nullptr, 1.0f, 1, MSIZE, EDIM);                        // 16
    softmax_rows<<<NROWS, 256>>>(sim, cvec);                             // 17
    sgemm_nn_add<<<dim3(EDIM / 128, NROWS / 128), 256>>>(sim, mv, x, h, NROWS, EDIM, MSIZE); // 18
    absmax_part<<<2048, 256>>>(h, nx / 4, part);                         // 19
    finalize_max<<<1, 256>>>(part, 2048, scal + 1);                      // 20
    quantize_act<<<(unsigned)(nx / 4 / 256), 256>>>(h, qx, scal + 1, nx / 4); // 21
    // out = wso*(hmax/127)*(qh@qwo^T) + bo
    imma_nt<<<dim3(EDIM / 128, NROWS / 128), 256>>>(qx, qwo, out, bo,
        scal + 3, scal + 1, 1.0f, 0, EDIM, EDIM);                        // 22
}

// round 9
// speedup vs baseline: 3.4687x; 2.6582x over previous
#include <cuda_runtime.h>
#include <cuda_bf16.h>
#include <cstddef>
#include <cstdint>

#define NROWS 32768
#define EDIM  1024
#define MSIZE 2048
typedef __nv_bfloat16 bf16;

// ---------------- scratch ----------------------------------------------------
__device__ float g_part[4096];
__device__ float g_scal[8];           // 0 xmax, 1 hmax, 2 wsk, 3 wso
__device__ bf16  g_qxb [(size_t)NROWS * EDIM];    // qx / qh as exact-int bf16
__device__ bf16  g_qwkT[(size_t)EDIM * EDIM];     // quantized Wk, transposed [i,d]
__device__ bf16  g_qwob[(size_t)EDIM * EDIM];     // quantized Wo [o,i]
__device__ bf16  g_mkhi[(size_t)MSIZE * EDIM];
__device__ bf16  g_mklo[(size_t)MSIZE * EDIM];
__device__ float g_G   [(size_t)MSIZE * EDIM];
__device__ bf16  g_ghi [(size_t)MSIZE * EDIM];
__device__ bf16  g_glo [(size_t)MSIZE * EDIM];
__device__ bf16  g_mhiT[(size_t)EDIM * MSIZE];
__device__ bf16  g_mloT[(size_t)EDIM * MSIZE];
__device__ float g_c   [MSIZE];
__device__ float g_sim [(size_t)NROWS * MSIZE];
__device__ bf16  g_ahi [(size_t)NROWS * MSIZE];
__device__ bf16  g_alo [(size_t)NROWS * MSIZE];
__device__ float g_h   [(size_t)NROWS * EDIM];

// ---------------- helpers ----------------------------------------------------
__device__ __forceinline__ uint32_t smem_u32(const void* p) {
    uint32_t a;
    asm("{ .reg .u64 t; cvta.to.shared.u64 t, %1; cvt.u32.u64 %0, t; }" : "=r"(a) : "l"(p));
    return a;
}
// 128B-row swizzle: 16B unit g ^= (row & 7)
__device__ __forceinline__ uint32_t sw_addr(uint32_t base, int r, int g) {
    return base + r * 128 + ((g ^ (r & 7)) << 4);
}
__device__ __forceinline__ void cp16(uint32_t s, const void* g) {
    asm volatile("cp.async.cg.shared.global [%0], [%1], 16;" :: "r"(s), "l"(g));
}
#define CP_COMMIT() asm volatile("cp.async.commit_group;" ::: "memory")
#define CP_WAIT0()  asm volatile("cp.async.wait_group 0;" ::: "memory")
#define LDSM4(r0, r1, r2, r3, addr) \
    asm volatile("ldmatrix.sync.aligned.m8n8.x4.shared.b16 {%0,%1,%2,%3}, [%4];" \
                 : "=r"(r0), "=r"(r1), "=r"(r2), "=r"(r3) : "r"(addr))
#define MMA_BF16(c, a, b0r, b1r) \
    asm volatile("mma.sync.aligned.m16n8k16.row.col.f32.bf16.bf16.f32 " \
                 "{%0,%1,%2,%3}, {%4,%5,%6,%7}, {%8,%9}, {%0,%1,%2,%3};" \
                 : "+f"((c)[0]), "+f"((c)[1]), "+f"((c)[2]), "+f"((c)[3]) \
                 : "r"((a)[0]), "r"((a)[1]), "r"((a)[2]), "r"((a)[3]), "r"(b0r), "r"(b1r))

// ---------------- reductions -------------------------------------------------
__global__ void absmax_part(const float* __restrict__ x, size_t n4, float* __restrict__ part) {
    const float4* x4 = (const float4*)x;
    float m = 0.f;
    for (size_t i = (size_t)blockIdx.x * blockDim.x + threadIdx.x; i < n4;
         i += (size_t)gridDim.x * blockDim.x) {
        float4 v = x4[i];
        m = fmaxf(m, fmaxf(fmaxf(fabsf(v.x), fabsf(v.y)), fmaxf(fabsf(v.z), fabsf(v.w))));
    }
    __shared__ float red[256];
    red[threadIdx.x] = m; __syncthreads();
    for (int s = 128; s > 0; s >>= 1) {
        if (threadIdx.x < s) red[threadIdx.x] = fmaxf(red[threadIdx.x], red[threadIdx.x + s]);
        __syncthreads();
    }
    if (threadIdx.x == 0) part[blockIdx.x] = red[0];
}

__global__ void abssum_part(const float* __restrict__ x, size_t n4, float* __restrict__ part) {
    const float4* x4 = (const float4*)x;
    float s = 0.f;
    for (size_t i = (size_t)blockIdx.x * blockDim.x + threadIdx.x; i < n4;
         i += (size_t)gridDim.x * blockDim.x) {
        float4 v = x4[i];
        s += fabsf(v.x) + fabsf(v.y) + fabsf(v.z) + fabsf(v.w);
    }
    __shared__ float red[256];
    red[threadIdx.x] = s; __syncthreads();
    for (int st = 128; st > 0; st >>= 1) {
        if (threadIdx.x < st) red[threadIdx.x] += red[threadIdx.x + st];
        __syncthreads();
    }
    if (threadIdx.x == 0) part[blockIdx.x] = red[0];
}

__global__ void finalize_max(const float* __restrict__ part, int npart, float* __restrict__ out) {
    __shared__ float red[256];
    float m = 0.f;
    for (int i = threadIdx.x; i < npart; i += 256) m = fmaxf(m, part[i]);
    red[threadIdx.x] = m; __syncthreads();
    for (int s = 128; s > 0; s >>= 1) {
        if (threadIdx.x < s) red[threadIdx.x] = fmaxf(red[threadIdx.x], red[threadIdx.x + s]);
        __syncthreads();
    }
    if (threadIdx.x == 0) out[0] = red[0];
}

__global__ void finalize_mean(const float* __restrict__ part, int npart, float* __restrict__ out, float n) {
    __shared__ float red[256];
    float s = 0.f;
    for (int i = threadIdx.x; i < npart; i += 256) s += part[i];
    red[threadIdx.x] = s; __syncthreads();
    for (int st = 128; st > 0; st >>= 1) {
        if (threadIdx.x < st) red[threadIdx.x] += red[threadIdx.x + st];
        __syncthreads();
    }
    if (threadIdx.x == 0) out[0] = __fdiv_rn(red[0], n);
}

// ---------------- quantize / split / transpose -------------------------------
__global__ void quantize_act_bf16(const float* __restrict__ x, bf16* __restrict__ q,
                                  const float* __restrict__ amax, size_t n4) {
    size_t i = (size_t)blockIdx.x * blockDim.x + threadIdx.x;
    if (i >= n4) return;
    float iscale = __fdiv_rn(amax[0], 127.0f);
    float4 v = ((const float4*)x)[i];
    float r0 = fminf(fmaxf(rintf(__fdiv_rn(v.x, iscale)), -128.f), 127.f);
    float r1 = fminf(fmaxf(rintf(__fdiv_rn(v.y, iscale)), -128.f), 127.f);
    float r2 = fminf(fmaxf(rintf(__fdiv_rn(v.z, iscale)), -128.f), 127.f);
    float r3 = fminf(fmaxf(rintf(__fdiv_rn(v.w, iscale)), -128.f), 127.f);
    bf16* o = q + i * 4;
    o[0] = __float2bfloat16(r0); o[1] = __float2bfloat16(r1);
    o[2] = __float2bfloat16(r2); o[3] = __float2bfloat16(r3);
}

__global__ void quantize_w_bf16(const float* __restrict__ W, bf16* __restrict__ q,
                                const float* __restrict__ wscale, size_t n) {
    size_t i = (size_t)blockIdx.x * blockDim.x + threadIdx.x;
    if (i >= n) return;
    float thr = 0.5f * wscale[0];
    float v = W[i];
    float o = (fabsf(v) > thr) ? (v > 0.f ? 1.f : -1.f) : 0.f;
    q[i] = __float2bfloat16(o);
}

// quantize Wk to bf16 ternary, transposed: q[i,d] = quant(W[d,i])
__global__ void tq_wkT(const float* __restrict__ W, bf16* __restrict__ q,
                       const float* __restrict__ scal) {
    __shared__ float t[32][33];
    int bd = blockIdx.y * 32, bi = blockIdx.x * 32;
    for (int j = threadIdx.y; j < 32; j += 8)
        t[j][threadIdx.x] = W[(size_t)(bd + j) * EDIM + bi + threadIdx.x];
    __syncthreads();
    float thr = 0.5f * scal[2];
    for (int j = threadIdx.y; j < 32; j += 8) {
        float v = t[threadIdx.x][j];
        float o = (fabsf(v) > thr) ? (v > 0.f ? 1.f : -1.f) : 0.f;
        q[(size_t)(bi + j) * EDIM + bd + threadIdx.x] = __float2bfloat16(o);
    }
}

// fp32 -> (hi, lo) bf16 split
__global__ void split2(const float* __restrict__ X, bf16* __restrict__ hi,
                       bf16* __restrict__ lo, size_t n) {
    size_t i = (size_t)blockIdx.x * blockDim.x + threadIdx.x;
    if (i >= n) return;
    float v = X[i];
    bf16 h = __float2bfloat16(v);
    hi[i] = h;
    lo[i] = __float2bfloat16(v - __bfloat162float(h));
}

// mv [MSIZE, EDIM] -> transposed split [EDIM, MSIZE]
__global__ void transpose_split(const float* __restrict__ mv, bf16* __restrict__ hi,
                                bf16* __restrict__ lo) {
    __shared__ float t[32][33];
    int bx = blockIdx.x * 32, by = blockIdx.y * 32;   // bx: e, by: m
    for (int i = threadIdx.y; i < 32; i += 8)
        t[i][threadIdx.x] = mv[(size_t)(by + i) * EDIM + bx + threadIdx.x];
    __syncthreads();
    for (int i = threadIdx.y; i < 32; i += 8) {
        float v = t[threadIdx.x][i];
        bf16 h = __float2bfloat16(v);
        size_t o = (size_t)(bx + i) * MSIZE + by + threadIdx.x;
        hi[o] = h;
        lo[o] = __float2bfloat16(v - __bfloat162float(h));
    }
}

__global__ void cvec_k(const float* __restrict__ mk, const float* __restrict__ bk,
                       float* __restrict__ c) {
    int m = blockIdx.x * 8 + (threadIdx.x >> 5);
    int lane = threadIdx.x & 31;
    const float4* row = (const float4*)(mk + (size_t)m * EDIM);
    const float4* b4 = (const float4*)bk;
    float s = 0.f;
    for (int i = lane; i < EDIM / 4; i += 32) {
        float4 a = row[i], b = b4[i];
        s += a.x * b.x + a.y * b.y + a.z * b.z + a.w * b.w;
    }
    for (int o = 16; o > 0; o >>= 1) s += __shfl_xor_sync(0xffffffffu, s, o);
    if (lane == 0) c[m] = s;
}

// -------- row softmax (+ c[m]/32), emit 2-level bf16 attn --------------------
__global__ void softmax_split(const float* __restrict__ S, const float* __restrict__ c,
                              bf16* __restrict__ ahi, bf16* __restrict__ alo) {
    const size_t row = blockIdx.x;
    const float* p = S + row * (size_t)MSIZE;
    const int tid = threadIdx.x;
    float v[8];
#pragma unroll
    for (int i = 0; i < 8; i++) v[i] = p[tid + i * 256] + c[tid + i * 256] * 0.03125f;
    float m = v[0];
#pragma unroll
    for (int i = 1; i < 8; i++) m = fmaxf(m, v[i]);
    __shared__ float red[256];
    red[tid] = m; __syncthreads();
    for (int s = 128; s > 0; s >>= 1) {
        if (tid < s) red[tid] = fmaxf(red[tid], red[tid + s]);
        __syncthreads();
    }
    const float rowmax = red[0];
    __syncthreads();
    float sum = 0.f;
#pragma unroll
    for (int i = 0; i < 8; i++) { v[i] = expf(v[i] - rowmax); sum += v[i]; }
    red[tid] = sum; __syncthreads();
    for (int s = 128; s > 0; s >>= 1) {
        if (tid < s) red[tid] += red[tid + s];
        __syncthreads();
    }
    const float inv = __fdiv_rn(1.0f, red[0]);
#pragma unroll
    for (int i = 0; i < 8; i++) {
        float a = v[i] * inv;
        bf16 h = __float2bfloat16(a);
        size_t o = row * (size_t)MSIZE + tid + i * 256;
        ahi[o] = h;
        alo[o] = __float2bfloat16(a - __bfloat162float(h));
    }
}

// ======= bf16 mma.sync GEMM NT, multi-pass register accumulate ===============
// D[128,128] = sum_p A_p[bm.., K] @ B_p[bn.., K]^T    (fp32 accum)
// mode 0: C = D*alpha0   (alpha0 = 0.03125*wsk*xmax/127)
// mode 1: C = D + aux (residual), block absmax -> part
// mode 2: C = D*alpha2 + aux[col]   (alpha2 = wso*hmax/127)
// mode 3: C = D
__device__ __forceinline__ void load_chunk(const bf16* A, const bf16* B, int K,
                                           int bm, int bn, int kc,
                                           uint32_t sA, uint32_t sB, int tid) {
    int r = tid >> 3, g = tid & 7;
    const bf16* ga = A + (size_t)(bm + r) * K + kc * 64 + g * 8;
    const bf16* gb = B + (size_t)(bn + r) * K + kc * 64 + g * 8;
#pragma unroll
    for (int i = 0; i < 4; i++) {
        cp16(sw_addr(sA, r + i * 32, g), ga + (size_t)i * 32 * K);
        cp16(sw_addr(sB, r + i * 32, g), gb + (size_t)i * 32 * K);
    }
}

__global__ __launch_bounds__(256)
void tc_gemm(const bf16* A0, const bf16* A1, const bf16* A2,
             const bf16* B0, const bf16* B1, const bf16* B2,
             int npass, int K, float* __restrict__ C, const float* __restrict__ aux,
             const float* __restrict__ scal, float* __restrict__ part, int mode, int M) {
    extern __shared__ char dsm[];
    __shared__ float red[256];
    const int tid = threadIdx.x, l = tid & 31, w = tid >> 5;
    const int bm = blockIdx.y * 128, bn = blockIdx.x * 128;
    const int wm = (w & 1) * 64, wn = (w >> 1) * 32;
    const int kchunks = K >> 6, total = npass * kchunks;
    const bf16* Ap[3] = {A0, A1, A2};
    const bf16* Bp[3] = {B0, B1, B2};
    const uint32_t sbase = smem_u32(dsm);

    float acc[4][4][4];
#pragma unroll
    for (int i = 0; i < 4; i++)
#pragma unroll
        for (int j = 0; j < 4; j++)
#pragma unroll
            for (int k = 0; k < 4; k++) acc[i][j][k] = 0.f;

    // prefetch chunk 0 into stage 0
    load_chunk(Ap[0], Bp[0], K, bm, bn, 0, sbase, sbase + 16384, tid);
    CP_COMMIT();
    CP_WAIT0();
    __syncthreads();

    for (int ch = 0; ch < total; ch++) {
        const int s = ch & 1;
        const uint32_t sA = sbase + s * 32768, sB = sA + 16384;
        if (ch + 1 < total) {
            int p = (ch + 1) / kchunks, kc = (ch + 1) % kchunks;
            uint32_t nA = sbase + (s ^ 1) * 32768;
            load_chunk(Ap[p], Bp[p], K, bm, bn, kc, nA, nA + 16384, tid);
            CP_COMMIT();
        }
        const int rA = wm + (l & 15);
        const int rB = wn + (l & 7) + ((l & 16) ? 8 : 0);
#pragma unroll
        for (int ks = 0; ks < 4; ks++) {
            uint32_t a[4][4], b[2][4];
            const int gA = ks * 2 + (l >> 4);
            const int gB = ks * 2 + ((l >> 3) & 1);
#pragma unroll
            for (int mt = 0; mt < 4; mt++)
                LDSM4(a[mt][0], a[mt][1], a[mt][2], a[mt][3], sw_addr(sA, rA + mt * 16, gA));
#pragma unroll
            for (int tp = 0; tp < 2; tp++)
                LDSM4(b[tp][0], b[tp][1], b[tp][2], b[tp][3], sw_addr(sB, rB + tp * 16, gB));
#pragma unroll
            for (int mt = 0; mt < 4; mt++)
#pragma unroll
                for (int nt = 0; nt < 4; nt++)
                    MMA_BF16(acc[mt][nt], a[mt], b[nt >> 1][(nt & 1) * 2], b[nt >> 1][(nt & 1) * 2 + 1]);
        }
        if (ch + 1 < total) CP_WAIT0();
        __syncthreads();
    }

    float alpha = 1.f;
    if (mode == 0) alpha = 0.03125f * scal[2] * __fdiv_rn(scal[0], 127.0f);
    else if (mode == 2) alpha = scal[3] * __fdiv_rn(scal[1], 127.0f);
    float lmax = 0.f;
    const int rr = bm + wm + (l >> 2);
    const int cb = bn + wn + (l & 3) * 2;
#pragma unroll
    for (int mt = 0; mt < 4; mt++) {
        int r0 = rr + mt * 16;
#pragma unroll
        for (int nt = 0; nt < 4; nt++) {
            int cc = cb + nt * 8;
            float* p0 = C + (size_t)r0 * M + cc;
            float* p1 = p0 + (size_t)8 * M;
            float v0 = acc[mt][nt][0], v1 = acc[mt][nt][1];
            float v2 = acc[mt][nt][2], v3 = acc[mt][nt][3];
            if (mode == 1) {
                const float* x0 = aux + (size_t)r0 * M + cc;
                const float* x1 = x0 + (size_t)8 * M;
                v0 += x0[0]; v1 += x0[1]; v2 += x1[0]; v3 += x1[1];
                lmax = fmaxf(lmax, fmaxf(fmaxf(fabsf(v0), fabsf(v1)), fmaxf(fabsf(v2), fabsf(v3))));
            } else if (mode == 0) {
                v0 *= alpha; v1 *= alpha; v2 *= alpha; v3 *= alpha;
            } else if (mode == 2) {
                float b0 = aux[cc], b1 = aux[cc + 1];
                v0 = v0 * alpha + b0; v1 = v1 * alpha + b1;
                v2 = v2 * alpha + b0; v3 = v3 * alpha + b1;
            }
            p0[0] = v0; p0[1] = v1; p1[0] = v2; p1[1] = v3;
        }
    }
    if (mode == 1) {
        red[tid] = lmax; __syncthreads();
        for (int s = 128; s > 0; s >>= 1) {
            if (tid < s) red[tid] = fmaxf(red[tid], red[tid + s]);
            __syncthreads();
        }
        if (tid == 0) part[blockIdx.y * gridDim.x + blockIdx.x] = red[0];
    }
}

// ---------------- launch -----------------------------------------------------
extern "C" void kernel_launch(void* const* d_in, const int* in_sizes, int n_in,
                              void* d_out, int out_size) {
    const float* x  = (const float*)d_in[0];
    const float* mk = (const float*)d_in[1];
    const float* mv = (const float*)d_in[2];
    const float* Wk = (const float*)d_in[3];
    const float* bk = (const float*)d_in[4];
    // d_in[5], d_in[6] (Wv, bv) dead: _query_values never reaches output.
    const float* Wo = (const float*)d_in[7];
    const float* bo = (const float*)d_in[8];
    float* out = (float*)d_out;

    void *a0,*a1,*a2,*a3,*a4,*a5,*a6,*a7,*a8,*a9,*a10,*a11,*a12,*a13,*a14,*a15,*a16;
    cudaGetSymbolAddress(&a0, g_part);  cudaGetSymbolAddress(&a1, g_scal);
    cudaGetSymbolAddress(&a2, g_qxb);   cudaGetSymbolAddress(&a3, g_qwkT);
    cudaGetSymbolAddress(&a4, g_qwob);  cudaGetSymbolAddress(&a5, g_G);
    cudaGetSymbolAddress(&a6, g_ghi);   cudaGetSymbolAddress(&a7, g_glo);
    cudaGetSymbolAddress(&a8, g_mhiT);  cudaGetSymbolAddress(&a9, g_mloT);
    cudaGetSymbolAddress(&a10, g_c);    cudaGetSymbolAddress(&a11, g_sim);
    cudaGetSymbolAddress(&a12, g_ahi);  cudaGetSymbolAddress(&a13, g_alo);
    cudaGetSymbolAddress(&a14, g_h);    cudaGetSymbolAddress(&a15, g_mkhi);
    cudaGetSymbolAddress(&a16, g_mklo);
    float* part = (float*)a0;  float* scal = (float*)a1;
    bf16* qxb = (bf16*)a2;     bf16* qwkT = (bf16*)a3;
    bf16* qwob = (bf16*)a4;    float* G = (float*)a5;
    bf16* ghi = (bf16*)a6;     bf16* glo = (bf16*)a7;
    bf16* mhiT = (bf16*)a8;    bf16* mloT = (bf16*)a9;
    float* cvec = (float*)a10; float* sim = (float*)a11;
    bf16* ahi = (bf16*)a12;    bf16* alo = (bf16*)a13;
    float* h = (float*)a14;
    bf16* mkhi = (bf16*)a15;   bf16* mklo = (bf16*)a16;

    const size_t nx = (size_t)NROWS * EDIM;
    const size_t nw = (size_t)EDIM * EDIM;
    const size_t ng = (size_t)MSIZE * EDIM;
    const int SMEM_TC = 65536;
    cudaFuncSetAttribute(tc_gemm, cudaFuncAttributeMaxDynamicSharedMemorySize, SMEM_TC);

    // 0: split mk -> hi/lo (exact to 2^-17)
    split2<<<(unsigned)((ng + 255) / 256), 256>>>(mk, mkhi, mklo, ng);
    // 1-2: wsk
    abssum_part<<<512, 256>>>(Wk, nw / 4, part + 2048);
    finalize_mean<<<1, 256>>>(part + 2048, 512, scal + 2, (float)nw);
    // 3: quantize+transpose Wk -> bf16 [i,d]
    tq_wkT<<<dim3(32, 32), dim3(32, 8)>>>(Wk, qwkT, scal);
    // 4: bias fold vector
    cvec_k<<<MSIZE / 8, 256>>>(mk, bk, cvec);
    // 5: G = (mkhi+mklo) @ qwkT^T   [2 passes]  <- ncu capture target
    tc_gemm<<<dim3(EDIM / 128, MSIZE / 128), 256, SMEM_TC>>>(
        mkhi, mklo, nullptr, qwkT, qwkT, nullptr, 2, EDIM, G, nullptr, scal, nullptr, 3, EDIM);
    // 6-8: xmax, qx
    absmax_part<<<2048, 256>>>(x, nx / 4, part);
    finalize_max<<<1, 256>>>(part, 2048, scal + 0);
    quantize_act_bf16<<<(unsigned)(nx / 4 / 256), 256>>>(x, qxb, scal + 0, nx / 4);
    // 9: split G
    split2<<<(unsigned)((ng + 255) / 256), 256>>>(G, ghi, glo, ng);
    // 10-12: wso, qWo
    abssum_part<<<512, 256>>>(Wo, nw / 4, part + 2560);
    finalize_mean<<<1, 256>>>(part + 2560, 512, scal + 3, (float)nw);
    quantize_w_bf16<<<(unsigned)(nw / 256), 256>>>(Wo, qwob, scal + 3, nw);
    // 13: mv transpose+split
    transpose_split<<<dim3(EDIM / 32, MSIZE / 32), dim3(32, 8)>>>(mv, mhiT, mloT);
    // 14: sim = alpha0 * qx @ (Ghi+Glo)^T   [2 passes]
    tc_gemm<<<dim3(MSIZE / 128, NROWS / 128), 256, SMEM_TC>>>(
        qxb, qxb, nullptr, ghi, glo, nullptr, 2, EDIM, sim, nullptr, scal, nullptr, 0, MSIZE);
    // 15: softmax -> attn hi/lo
    softmax_split<<<NROWS, 256>>>(sim, cvec, ahi, alo);
    // 16: h = x + ahi@mhi + alo@mhi + ahi@mlo  [3 passes] + fused absmax
    tc_gemm<<<dim3(EDIM / 128, NROWS / 128), 256, SMEM_TC>>>(
        ahi, alo, ahi, mhiT, mhiT, mloT, 3, MSIZE, h, x, scal, part, 1, EDIM);
    // 17: hmax
    finalize_max<<<1, 256>>>(part, (EDIM / 128) * (NROWS / 128), scal + 1);
    // 18: qh
    quantize_act_bf16<<<(unsigned)(nx / 4 / 256), 256>>>(h, qxb, scal + 1, nx / 4);
    // 19: out = alpha2 * qh @ qWo^T + bo   [exact]
    tc_gemm<<<dim3(EDIM / 128, NROWS / 128), 256, SMEM_TC>>>(
        qxb, nullptr, nullptr, qwob, nullptr, nullptr, 1, EDIM, out, bo, scal, nullptr, 2, EDIM);
}